// round 1
// baseline (speedup 1.0000x reference)
#include <cuda_runtime.h>
#include <cstdint>

#define NNODES 100000
#define NEDGES 1600000
#define DIM 128
#define NGRAPHS 128
#define NLAYERS 3
#define BN_EPS 1e-5f

// ---------------- scratch (static device globals; no allocation) -------------
__device__ float g_aggr[(size_t)NNODES * DIM];   // aggr buffer, then reused as h (GEMM2 out)
__device__ float g_tmp[(size_t)NNODES * DIM];    // GEMM1 output
__device__ float g_sum[DIM];
__device__ float g_sumsq[DIM];
__device__ float g_scale[DIM];
__device__ float g_shift[DIM];

// ---------------- zero aggr + stats ------------------------------------------
__global__ void k_zero() {
    size_t i = (size_t)blockIdx.x * blockDim.x + threadIdx.x;
    size_t stride = (size_t)gridDim.x * blockDim.x;
    float4* p = (float4*)g_aggr;
    const size_t n4 = (size_t)NNODES * DIM / 4;
    float4 z = make_float4(0.f, 0.f, 0.f, 0.f);
    for (size_t j = i; j < n4; j += stride) p[j] = z;
    if (blockIdx.x == 0 && threadIdx.x < DIM) {
        g_sum[threadIdx.x] = 0.f;
        g_sumsq[threadIdx.x] = 0.f;
    }
}

__global__ void k_zero_gcat(float* gcat) {
    int i = blockIdx.x * blockDim.x + threadIdx.x;
    if (i < NGRAPHS * NLAYERS * DIM) gcat[i] = 0.f;
}

// ---------------- edge scatter: aggr[dst] += z[src] ---------------------------
// one warp per edge (grid-stride); 16B vector reduction per lane.
__global__ void k_scatter(const float* __restrict__ zin, int pin,
                          const int* __restrict__ ei) {
    const int lane = threadIdx.x & 31;
    int w = (blockIdx.x * blockDim.x + threadIdx.x) >> 5;
    const int nw = (gridDim.x * blockDim.x) >> 5;
    for (int e = w; e < NEDGES; e += nw) {
        const int s = ei[e];
        const int d = ei[NEDGES + e];
        const float4 v = *(const float4*)(zin + (size_t)s * pin + lane * 4);
        float* p = g_aggr + (size_t)d * DIM + lane * 4;
        asm volatile("red.global.add.v4.f32 [%0], {%1, %2, %3, %4};"
                     :: "l"(p), "f"(v.x), "f"(v.y), "f"(v.z), "f"(v.w)
                     : "memory");
    }
}

// ---------------- fused GEMM: out = relu((A [+ B]) @ W + bias) ---------------
// Tile: 64 rows x 128 cols. 256 threads, each computes 4 rows x 8 cols using
// packed fma.rn.f32x2 (FFMA2 is full-rate; FFMA-3reg is half rate on sm_10x).
#define AS_PITCH 132
#define GEMM_SMEM ((DIM * DIM + 64 * AS_PITCH) * 4)

__global__ void k_gemm(const float* __restrict__ A, int pA,
                       const float* __restrict__ B,        // optional, pitch 128
                       const float* __restrict__ W,        // [128][128] row-major
                       const float* __restrict__ bias,     // [128]
                       float* __restrict__ out,            // pitch 128
                       int nrows) {
    extern __shared__ float sm[];
    float* ws = sm;                 // 128*128
    float* as = sm + DIM * DIM;     // 64*132

    const int tid = threadIdx.x;
    const int row0 = blockIdx.x * 64;

    // load W (16384 floats = 4096 float4; 16 per thread)
    {
        const float4* Wv = (const float4*)W;
        float4* wv = (float4*)ws;
        #pragma unroll
        for (int i = 0; i < 16; i++) wv[tid + i * 256] = Wv[tid + i * 256];
    }
    // load A tile (+B) : 64x128 = 2048 float4; 8 per thread
    {
        #pragma unroll
        for (int i = 0; i < 8; i++) {
            int fi = tid + i * 256;
            int r = fi >> 5;
            int c = (fi & 31) << 2;
            int gr = row0 + r;
            float4 v = make_float4(0.f, 0.f, 0.f, 0.f);
            if (gr < nrows) {
                v = *(const float4*)(A + (size_t)gr * pA + c);
                if (B) {
                    float4 b4 = *(const float4*)(B + (size_t)gr * DIM + c);
                    v.x += b4.x; v.y += b4.y; v.z += b4.z; v.w += b4.w;
                }
            }
            *(float4*)(as + r * AS_PITCH + c) = v;
        }
    }
    __syncthreads();

    const int cg = tid & 15;        // 16 col groups of 8
    const int rg = tid >> 4;        // 16 row groups of 4
    const int c0 = cg * 8;
    const int r0 = rg * 4;

    unsigned long long acc[4][4];
    #pragma unroll
    for (int r = 0; r < 4; r++)
        #pragma unroll
        for (int c = 0; c < 4; c++) acc[r][c] = 0ULL;

    #pragma unroll 8
    for (int k = 0; k < DIM; k++) {
        unsigned long long aa[4];
        #pragma unroll
        for (int r = 0; r < 4; r++) {
            float a = as[(r0 + r) * AS_PITCH + k];
            asm("mov.b64 %0, {%1, %1};" : "=l"(aa[r]) : "f"(a));
        }
        const ulonglong2* wp = (const ulonglong2*)(ws + k * DIM + c0);
        ulonglong2 wA = wp[0];
        ulonglong2 wB = wp[1];
        unsigned long long wv[4];
        wv[0] = wA.x; wv[1] = wA.y; wv[2] = wB.x; wv[3] = wB.y;
        #pragma unroll
        for (int r = 0; r < 4; r++)
            #pragma unroll
            for (int c = 0; c < 4; c++)
                asm("fma.rn.f32x2 %0, %1, %2, %0;"
                    : "+l"(acc[r][c]) : "l"(aa[r]), "l"(wv[c]));
    }

    // epilogue: +bias, relu, store
    float bb[8];
    #pragma unroll
    for (int c = 0; c < 8; c++) bb[c] = __ldg(&bias[c0 + c]);

    #pragma unroll
    for (int r = 0; r < 4; r++) {
        int gr = row0 + r0 + r;
        if (gr >= nrows) break;
        float o[8];
        #pragma unroll
        for (int c = 0; c < 4; c++) {
            float lo, hi;
            asm("mov.b64 {%0, %1}, %2;" : "=f"(lo), "=f"(hi) : "l"(acc[r][c]));
            o[2 * c]     = fmaxf(lo + bb[2 * c], 0.f);
            o[2 * c + 1] = fmaxf(hi + bb[2 * c + 1], 0.f);
        }
        float4* po = (float4*)(out + (size_t)gr * DIM + c0);
        po[0] = make_float4(o[0], o[1], o[2], o[3]);
        po[1] = make_float4(o[4], o[5], o[6], o[7]);
    }
}

// ---------------- batchnorm stats (sum, sumsq per feature) -------------------
#define STAT_CH 512
__global__ void k_stats(const float* __restrict__ h) {
    const int f = threadIdx.x & 127;
    const int ln = threadIdx.x >> 7;        // 0..3
    const int r0 = blockIdx.x * STAT_CH;
    const int rend = min(r0 + STAT_CH, NNODES);
    float s = 0.f, ss = 0.f;
    for (int r = r0 + ln; r < rend; r += 4) {
        float v = h[(size_t)r * DIM + f];
        s += v;
        ss += v * v;
    }
    atomicAdd(&g_sum[f], s);
    atomicAdd(&g_sumsq[f], ss);
}

__global__ void k_finalize(const float* __restrict__ gamma,
                           const float* __restrict__ beta) {
    int f = threadIdx.x;
    float mean = g_sum[f] * (1.0f / NNODES);
    float var = g_sumsq[f] * (1.0f / NNODES) - mean * mean;
    float inv = rsqrtf(var + BN_EPS);
    float sc = gamma[f] * inv;
    g_scale[f] = sc;
    g_shift[f] = beta[f] - mean * sc;
}

// ---------------- normalize + write z_cat slice + graph add-pool -------------
#define NP_CH 512
__global__ void k_norm_pool(const float* __restrict__ h,
                            const int* __restrict__ batch,
                            float* __restrict__ zout,   // z_cat + l*128, pitch 384
                            float* __restrict__ gout) { // g_cat + l*128, pitch 384
    const int f = threadIdx.x & 127;
    const int ln = threadIdx.x >> 7;        // 0..3
    const int r0 = blockIdx.x * NP_CH;
    const int rend = min(r0 + NP_CH, NNODES);
    const float sc = g_scale[f];
    const float sh = g_shift[f];
    float acc = 0.f;
    int cur = -1;
    for (int r = r0 + ln; r < rend; r += 4) {
        float v = fmaf(h[(size_t)r * DIM + f], sc, sh);
        zout[(size_t)r * (NLAYERS * DIM) + f] = v;
        int b = batch[r];
        if (b != cur) {
            if (cur >= 0) atomicAdd(&gout[(size_t)cur * (NLAYERS * DIM) + f], acc);
            cur = b;
            acc = v;
        } else {
            acc += v;
        }
    }
    if (cur >= 0) atomicAdd(&gout[(size_t)cur * (NLAYERS * DIM) + f], acc);
}

// ---------------- launch ------------------------------------------------------
extern "C" void kernel_launch(void* const* d_in, const int* in_sizes, int n_in,
                              void* d_out, int out_size) {
    const float* x     = (const float*)d_in[0];
    const int*   ei    = (const int*)d_in[1];
    const int*   batch = (const int*)d_in[2];
    const float* W1    = (const float*)d_in[3];
    const float* b1    = (const float*)d_in[4];
    const float* W2    = (const float*)d_in[5];
    const float* b2    = (const float*)d_in[6];
    const float* gamma = (const float*)d_in[7];
    const float* beta  = (const float*)d_in[8];

    float* z_cat = (float*)d_out;                               // [N, 384]
    float* g_cat = z_cat + (size_t)NNODES * NLAYERS * DIM;      // [128, 384]

    cudaFuncSetAttribute(k_gemm, cudaFuncAttributeMaxDynamicSharedMemorySize,
                         GEMM_SMEM);

    float* aggr;  cudaGetSymbolAddress((void**)&aggr, g_aggr);
    float* tmp;   cudaGetSymbolAddress((void**)&tmp, g_tmp);

    k_zero_gcat<<<(NGRAPHS * NLAYERS * DIM + 255) / 256, 256>>>(g_cat);

    const int gemm_grid = (NNODES + 63) / 64;
    const int stat_grid = (NNODES + STAT_CH - 1) / STAT_CH;
    const int np_grid   = (NNODES + NP_CH - 1) / NP_CH;

    for (int l = 0; l < NLAYERS; l++) {
        const float* zin = (l == 0) ? x : (z_cat + (size_t)(l - 1) * DIM);
        const int pin = (l == 0) ? DIM : (NLAYERS * DIM);

        k_zero<<<1184, 256>>>();
        k_scatter<<<4736, 256>>>(zin, pin, ei);
        // GEMM1: tmp = relu((zin + aggr) @ W1 + b1)
        k_gemm<<<gemm_grid, 256, GEMM_SMEM>>>(zin, pin, aggr,
                                              W1 + (size_t)l * DIM * DIM,
                                              b1 + (size_t)l * DIM, tmp, NNODES);
        // GEMM2: h (reuses aggr) = relu(tmp @ W2 + b2)
        k_gemm<<<gemm_grid, 256, GEMM_SMEM>>>(tmp, DIM, nullptr,
                                              W2 + (size_t)l * DIM * DIM,
                                              b2 + (size_t)l * DIM, aggr, NNODES);
        k_stats<<<stat_grid, 512>>>(aggr);
        k_finalize<<<1, 128>>>(gamma + (size_t)l * DIM, beta + (size_t)l * DIM);
        k_norm_pool<<<np_grid, 512>>>(aggr, batch,
                                      z_cat + (size_t)l * DIM,
                                      g_cat + (size_t)l * DIM);
    }
}

// round 2
// speedup vs baseline: 1.4763x; 1.4763x over previous
#include <cuda_runtime.h>
#include <cstdint>

#define NNODES 100000
#define NEDGES 1600000
#define DIM 128
#define NGRAPHS 128
#define NLAYERS 3
#define BN_EPS 1e-5f

// ---------------- scratch (static device globals; no allocation) -------------
__device__ float g_aggr[(size_t)NNODES * DIM];   // aggr (incl self); reused as h (GEMM2 out)
__device__ float g_tmp[(size_t)NNODES * DIM];    // GEMM1 output
__device__ float g_sum[DIM];
__device__ float g_sumsq[DIM];
__device__ float g_scale[DIM];
__device__ float g_shift[DIM];

// CSR by destination
__device__ int g_cnt[NNODES];
__device__ int g_rowptr[NNODES + 1];
__device__ int g_cur[NNODES];
__device__ int g_srcbuf[NEDGES];

// ---------------- CSR construction -------------------------------------------
__global__ void k_zero_cnt() {
    int i = blockIdx.x * blockDim.x + threadIdx.x;
    int stride = gridDim.x * blockDim.x;
    for (int j = i; j < NNODES; j += stride) g_cnt[j] = 0;
}

__global__ void k_hist(const int* __restrict__ ei) {
    int i = blockIdx.x * blockDim.x + threadIdx.x;
    int stride = gridDim.x * blockDim.x;
    for (int e = i; e < NEDGES; e += stride)
        atomicAdd(&g_cnt[ei[NEDGES + e]], 1);
}

// single-block exclusive scan over g_cnt -> g_rowptr, g_cur
__global__ void k_scan() {
    __shared__ int warp_sums[32];
    __shared__ int carry;
    const int tid = threadIdx.x;
    const int lane = tid & 31;
    const int wid = tid >> 5;
    if (tid == 0) carry = 0;
    __syncthreads();
    for (int base = 0; base < NNODES; base += 1024) {
        int i = base + tid;
        int v = (i < NNODES) ? g_cnt[i] : 0;
        int x = v;
        #pragma unroll
        for (int o = 1; o < 32; o <<= 1) {
            int t = __shfl_up_sync(~0u, x, o);
            if (lane >= o) x += t;
        }
        if (lane == 31) warp_sums[wid] = x;
        __syncthreads();                       // A: partials ready
        if (wid == 0) {
            int s = warp_sums[lane];
            #pragma unroll
            for (int o = 1; o < 32; o <<= 1) {
                int t = __shfl_up_sync(~0u, s, o);
                if (lane >= o) s += t;
            }
            warp_sums[lane] = s;
        }
        __syncthreads();                       // B: warp_sums scanned
        int incl = x + (wid > 0 ? warp_sums[wid - 1] : 0);
        int excl = carry + incl - v;
        if (i < NNODES) { g_rowptr[i] = excl; g_cur[i] = excl; }
        __syncthreads();                       // C: all reads of carry done
        if (tid == 0) carry += warp_sums[31];
        __syncthreads();                       // D: carry visible, warp_sums reusable
    }
    if (tid == 0) g_rowptr[NNODES] = carry;
}

__global__ void k_fill(const int* __restrict__ ei) {
    int i = blockIdx.x * blockDim.x + threadIdx.x;
    int stride = gridDim.x * blockDim.x;
    for (int e = i; e < NEDGES; e += stride) {
        int d = ei[NEDGES + e];
        int pos = atomicAdd(&g_cur[d], 1);
        g_srcbuf[pos] = ei[e];
    }
}

// ---------------- gather aggregation: aggr[n] = z[n] + sum_{j->n} z[j] --------
__global__ void k_aggregate(const float* __restrict__ zin, int pin) {
    const int lane = threadIdx.x & 31;
    const int w = (blockIdx.x * blockDim.x + threadIdx.x) >> 5;
    if (w >= NNODES) return;
    const int c = lane * 4;
    const int beg = g_rowptr[w];
    const int end = g_rowptr[w + 1];
    float4 a0 = *(const float4*)(zin + (size_t)w * pin + c);   // self
    float4 a1 = make_float4(0.f, 0.f, 0.f, 0.f);
    float4 a2 = a1, a3 = a1;
    int e = beg;
    for (; e + 4 <= end; e += 4) {
        int s0 = g_srcbuf[e], s1 = g_srcbuf[e + 1];
        int s2 = g_srcbuf[e + 2], s3 = g_srcbuf[e + 3];
        float4 v0 = *(const float4*)(zin + (size_t)s0 * pin + c);
        float4 v1 = *(const float4*)(zin + (size_t)s1 * pin + c);
        float4 v2 = *(const float4*)(zin + (size_t)s2 * pin + c);
        float4 v3 = *(const float4*)(zin + (size_t)s3 * pin + c);
        a0.x += v0.x; a0.y += v0.y; a0.z += v0.z; a0.w += v0.w;
        a1.x += v1.x; a1.y += v1.y; a1.z += v1.z; a1.w += v1.w;
        a2.x += v2.x; a2.y += v2.y; a2.z += v2.z; a2.w += v2.w;
        a3.x += v3.x; a3.y += v3.y; a3.z += v3.z; a3.w += v3.w;
    }
    for (; e < end; e++) {
        int s = g_srcbuf[e];
        float4 v = *(const float4*)(zin + (size_t)s * pin + c);
        a0.x += v.x; a0.y += v.y; a0.z += v.z; a0.w += v.w;
    }
    a0.x += a1.x + a2.x + a3.x;
    a0.y += a1.y + a2.y + a3.y;
    a0.z += a1.z + a2.z + a3.z;
    a0.w += a1.w + a2.w + a3.w;
    *(float4*)(g_aggr + (size_t)w * DIM + c) = a0;
}

// ---------------- GEMM: out = relu(A @ W + bias) ------------------------------
// Tile 64x128, 256 threads, thread tile 4 rows x 8 cols (cols c0..c0+3, c0+64..c0+67).
// k unrolled by 4: A via LDS.128 (broadcast), W via conflict-free contiguous LDS.128.
#define AS_PITCH 132
#define GEMM_SMEM ((DIM * DIM + 64 * AS_PITCH) * 4)

__global__ void k_gemm(const float* __restrict__ A,
                       const float* __restrict__ W,
                       const float* __restrict__ bias,
                       float* __restrict__ out,
                       int nrows) {
    extern __shared__ float sm[];
    float* ws = sm;                 // 128*128
    float* as = sm + DIM * DIM;     // 64*132

    const int tid = threadIdx.x;
    const int row0 = blockIdx.x * 64;

    // load W: 4096 float4, 16 per thread
    {
        const float4* Wv = (const float4*)W;
        float4* wv = (float4*)ws;
        #pragma unroll
        for (int i = 0; i < 16; i++) wv[tid + i * 256] = Wv[tid + i * 256];
    }
    // load A tile: 64x128 = 2048 float4, 8 per thread
    {
        #pragma unroll
        for (int i = 0; i < 8; i++) {
            int fi = tid + i * 256;
            int r = fi >> 5;
            int c = (fi & 31) << 2;
            int gr = row0 + r;
            float4 v = make_float4(0.f, 0.f, 0.f, 0.f);
            if (gr < nrows) v = *(const float4*)(A + (size_t)gr * DIM + c);
            *(float4*)(as + r * AS_PITCH + c) = v;
        }
    }
    __syncthreads();

    const int c0 = (tid & 15) * 4;
    const int r0 = (tid >> 4) * 4;

    // acc[r][0]: cols c0,c0+1; [1]: c0+2,c0+3; [2]: c0+64,65; [3]: c0+66,67
    unsigned long long acc[4][4];
    #pragma unroll
    for (int r = 0; r < 4; r++)
        #pragma unroll
        for (int c = 0; c < 4; c++) acc[r][c] = 0ULL;

    #pragma unroll 4
    for (int k0 = 0; k0 < DIM; k0 += 4) {
        float4 a4[4];
        #pragma unroll
        for (int r = 0; r < 4; r++)
            a4[r] = *(const float4*)(as + (r0 + r) * AS_PITCH + k0);
        #pragma unroll
        for (int kk = 0; kk < 4; kk++) {
            const float* wrow = ws + (k0 + kk) * DIM;
            ulonglong2 w0 = *(const ulonglong2*)(wrow + c0);
            ulonglong2 w1 = *(const ulonglong2*)(wrow + c0 + 64);
            #pragma unroll
            for (int r = 0; r < 4; r++) {
                float a = (&a4[r].x)[kk];
                unsigned long long aa;
                asm("mov.b64 %0, {%1, %1};" : "=l"(aa) : "f"(a));
                asm("fma.rn.f32x2 %0, %1, %2, %0;" : "+l"(acc[r][0]) : "l"(aa), "l"(w0.x));
                asm("fma.rn.f32x2 %0, %1, %2, %0;" : "+l"(acc[r][1]) : "l"(aa), "l"(w0.y));
                asm("fma.rn.f32x2 %0, %1, %2, %0;" : "+l"(acc[r][2]) : "l"(aa), "l"(w1.x));
                asm("fma.rn.f32x2 %0, %1, %2, %0;" : "+l"(acc[r][3]) : "l"(aa), "l"(w1.y));
            }
        }
    }

    // epilogue: +bias, relu, store
    float b0[4], b1[4];
    #pragma unroll
    for (int j = 0; j < 4; j++) {
        b0[j] = __ldg(&bias[c0 + j]);
        b1[j] = __ldg(&bias[c0 + 64 + j]);
    }
    #pragma unroll
    for (int r = 0; r < 4; r++) {
        int gr = row0 + r0 + r;
        if (gr >= nrows) break;
        float o0[4], o1[4];
        #pragma unroll
        for (int c = 0; c < 2; c++) {
            float lo, hi;
            asm("mov.b64 {%0, %1}, %2;" : "=f"(lo), "=f"(hi) : "l"(acc[r][c]));
            o0[2 * c]     = fmaxf(lo + b0[2 * c], 0.f);
            o0[2 * c + 1] = fmaxf(hi + b0[2 * c + 1], 0.f);
            asm("mov.b64 {%0, %1}, %2;" : "=f"(lo), "=f"(hi) : "l"(acc[r][c + 2]));
            o1[2 * c]     = fmaxf(lo + b1[2 * c], 0.f);
            o1[2 * c + 1] = fmaxf(hi + b1[2 * c + 1], 0.f);
        }
        *(float4*)(out + (size_t)gr * DIM + c0)      = make_float4(o0[0], o0[1], o0[2], o0[3]);
        *(float4*)(out + (size_t)gr * DIM + c0 + 64) = make_float4(o1[0], o1[1], o1[2], o1[3]);
    }
}

// ---------------- batchnorm stats ---------------------------------------------
__global__ void k_zero_stats() {
    if (threadIdx.x < DIM) {
        g_sum[threadIdx.x] = 0.f;
        g_sumsq[threadIdx.x] = 0.f;
    }
}

#define STAT_CH 512
__global__ void k_stats(const float* __restrict__ h) {
    const int f = threadIdx.x & 127;
    const int ln = threadIdx.x >> 7;
    const int r0 = blockIdx.x * STAT_CH;
    const int rend = min(r0 + STAT_CH, NNODES);
    float s = 0.f, ss = 0.f;
    for (int r = r0 + ln; r < rend; r += 4) {
        float v = h[(size_t)r * DIM + f];
        s += v;
        ss += v * v;
    }
    atomicAdd(&g_sum[f], s);
    atomicAdd(&g_sumsq[f], ss);
}

__global__ void k_finalize(const float* __restrict__ gamma,
                           const float* __restrict__ beta) {
    int f = threadIdx.x;
    float mean = g_sum[f] * (1.0f / NNODES);
    float var = g_sumsq[f] * (1.0f / NNODES) - mean * mean;
    float inv = rsqrtf(var + BN_EPS);
    float sc = gamma[f] * inv;
    g_scale[f] = sc;
    g_shift[f] = beta[f] - mean * sc;
}

// ---------------- normalize + z_cat slice + graph add-pool --------------------
__global__ void k_zero_gcat(float* gcat) {
    int i = blockIdx.x * blockDim.x + threadIdx.x;
    if (i < NGRAPHS * NLAYERS * DIM) gcat[i] = 0.f;
}

#define NP_CH 512
__global__ void k_norm_pool(const float* __restrict__ h,
                            const int* __restrict__ batch,
                            float* __restrict__ zout,
                            float* __restrict__ gout) {
    const int f = threadIdx.x & 127;
    const int ln = threadIdx.x >> 7;
    const int r0 = blockIdx.x * NP_CH;
    const int rend = min(r0 + NP_CH, NNODES);
    const float sc = g_scale[f];
    const float sh = g_shift[f];
    float acc = 0.f;
    int cur = -1;
    for (int r = r0 + ln; r < rend; r += 4) {
        float v = fmaf(h[(size_t)r * DIM + f], sc, sh);
        zout[(size_t)r * (NLAYERS * DIM) + f] = v;
        int b = batch[r];
        if (b != cur) {
            if (cur >= 0) atomicAdd(&gout[(size_t)cur * (NLAYERS * DIM) + f], acc);
            cur = b;
            acc = v;
        } else {
            acc += v;
        }
    }
    if (cur >= 0) atomicAdd(&gout[(size_t)cur * (NLAYERS * DIM) + f], acc);
}

// ---------------- launch -------------------------------------------------------
extern "C" void kernel_launch(void* const* d_in, const int* in_sizes, int n_in,
                              void* d_out, int out_size) {
    const float* x     = (const float*)d_in[0];
    const int*   ei    = (const int*)d_in[1];
    const int*   batch = (const int*)d_in[2];
    const float* W1    = (const float*)d_in[3];
    const float* b1    = (const float*)d_in[4];
    const float* W2    = (const float*)d_in[5];
    const float* b2    = (const float*)d_in[6];
    const float* gamma = (const float*)d_in[7];
    const float* beta  = (const float*)d_in[8];

    float* z_cat = (float*)d_out;                               // [N, 384]
    float* g_cat = z_cat + (size_t)NNODES * NLAYERS * DIM;      // [128, 384]

    cudaFuncSetAttribute(k_gemm, cudaFuncAttributeMaxDynamicSharedMemorySize,
                         GEMM_SMEM);

    float* aggr;  cudaGetSymbolAddress((void**)&aggr, g_aggr);
    float* tmp;   cudaGetSymbolAddress((void**)&tmp, g_tmp);

    // CSR build (once per call; reused by all 3 layers)
    k_zero_cnt<<<128, 512>>>();
    k_hist<<<1024, 512>>>(ei);
    k_scan<<<1, 1024>>>();
    k_fill<<<1024, 512>>>(ei);

    k_zero_gcat<<<(NGRAPHS * NLAYERS * DIM + 255) / 256, 256>>>(g_cat);

    const int gemm_grid = (NNODES + 63) / 64;
    const int stat_grid = (NNODES + STAT_CH - 1) / STAT_CH;
    const int np_grid   = (NNODES + NP_CH - 1) / NP_CH;
    const int agg_grid  = (NNODES * 32 + 255) / 256;   // warp per node

    for (int l = 0; l < NLAYERS; l++) {
        const float* zin = (l == 0) ? x : (z_cat + (size_t)(l - 1) * DIM);
        const int pin = (l == 0) ? DIM : (NLAYERS * DIM);

        k_aggregate<<<agg_grid, 256>>>(zin, pin);
        // GEMM1: tmp = relu(aggr @ W1 + b1)
        k_gemm<<<gemm_grid, 256, GEMM_SMEM>>>(aggr,
                                              W1 + (size_t)l * DIM * DIM,
                                              b1 + (size_t)l * DIM, tmp, NNODES);
        // GEMM2: h (reuses aggr) = relu(tmp @ W2 + b2)
        k_gemm<<<gemm_grid, 256, GEMM_SMEM>>>(tmp,
                                              W2 + (size_t)l * DIM * DIM,
                                              b2 + (size_t)l * DIM, aggr, NNODES);
        k_zero_stats<<<1, 128>>>();
        k_stats<<<stat_grid, 512>>>(aggr);
        k_finalize<<<1, 128>>>(gamma + (size_t)l * DIM, beta + (size_t)l * DIM);
        k_norm_pool<<<np_grid, 512>>>(aggr, batch,
                                      z_cat + (size_t)l * DIM,
                                      g_cat + (size_t)l * DIM);
    }
}